// round 2
// baseline (speedup 1.0000x reference)
#include <cuda_runtime.h>
#include <cstdint>
#include <cstddef>

// Problem constants
#define Bn 4
#define Cn 128
#define Hn 128
#define Wn 256
#define Dn 81
#define TH 4       // output rows per block
#define TWt 128    // output cols per block
#define NTHREADS 384  // 12 warps: 3 di-groups x 4 rows; each thread = 4-pixel strip

// ---------- f32x2 helpers ----------
__device__ __forceinline__ unsigned long long pk2(float lo, float hi) {
    unsigned long long r;
    asm("mov.b64 %0, {%1, %2};" : "=l"(r) : "f"(lo), "f"(hi));
    return r;
}
__device__ __forceinline__ void fma2(unsigned long long &d, unsigned long long a, unsigned long long b) {
    asm("fma.rn.f32x2 %0, %1, %2, %0;" : "+l"(d) : "l"(a), "l"(b));
}
__device__ __forceinline__ void upk2(unsigned long long v, float &lo, float &hi) {
    asm("mov.b64 {%0, %1}, %2;" : "=f"(lo), "=f"(hi) : "l"(v));
}
// cp.async 16B with zero-fill predication (src-size = 0 -> 16 zeros, no read)
__device__ __forceinline__ void cp16(void* dst_smem, const void* src, bool ok) {
    unsigned dst = (unsigned)__cvta_generic_to_shared(dst_smem);
    int sz = ok ? 16 : 0;
    asm volatile("cp.async.ca.shared.global [%0], [%1], 16, %2;" :: "r"(dst), "l"(src), "r"(sz));
}

__global__ void __launch_bounds__(NTHREADS, 1)
cost_volume_kernel(const float* __restrict__ x1,
                   const float* __restrict__ x2,
                   float* __restrict__ out)
{
    // x2 tile: rows h0-4 .. h0+7 (12), cols w0-4 .. w0+131 (136), double buffered
    __shared__ __align__(16) float x2s[2][12][136];
    __shared__ __align__(16) float x1s[2][TH][TWt];

    const int tid  = threadIdx.x;
    const int lane = tid & 31;
    const int warp = tid >> 5;     // 0..11
    const int g    = warp >> 2;    // di-group 0..2 (di = 3g+rr-4)
    const int row  = warp & 3;     // output row within tile

    const int w0 = blockIdx.x * TWt;
    const int h0 = blockIdx.y * TH;
    const int bb = blockIdx.z;

    // 27 (rr,dj) x 2 pixel-pairs, f32x2 each
    unsigned long long acc[54];
#pragma unroll
    for (int i = 0; i < 54; ++i) acc[i] = 0ull;

    // ---- channel-tile loader: 408 x2 chunks + 128 x1 chunks of 16B ----
    auto load_chan = [&](int buf, int c) {
        const float* x2base = x2 + (size_t)(bb * Cn + c) * (Hn * Wn);
        const float* x1base = x1 + (size_t)(bb * Cn + c) * (Hn * Wn);
#pragma unroll
        for (int s = 0; s < 2; ++s) {
            int id = tid + s * NTHREADS;
            if (id < 408) {
                int rw = id / 34;
                int c4 = id - rw * 34;
                int hs = h0 - 4 + rw;
                int ws = w0 - 4 + c4 * 4;
                bool ok = ((unsigned)hs < (unsigned)Hn) && ((unsigned)ws < (unsigned)Wn);
                const float* src = ok ? (x2base + hs * Wn + ws) : x2base;
                cp16(&x2s[buf][rw][c4 * 4], src, ok);
            } else if (id < 536) {
                int j  = id - 408;
                int rw = j >> 5;
                int c4 = j & 31;
                const float* src = x1base + (h0 + rw) * Wn + w0 + c4 * 4;
                cp16(&x1s[buf][rw][c4 * 4], src, true);
            }
        }
        asm volatile("cp.async.commit_group;");
    };

    load_chan(0, 0);

#pragma unroll 1
    for (int c = 0; c < Cn; ++c) {
        const int buf = c & 1;
        if (c + 1 < Cn) {
            load_chan(buf ^ 1, c + 1);
            asm volatile("cp.async.wait_group 1;");
        } else {
            asm volatile("cp.async.wait_group 0;");
        }
        __syncthreads();

        // x1 values for this thread's 4 pixels
        const float4* x1r = reinterpret_cast<const float4*>(&x1s[buf][row][0]);
        float4 xv = x1r[lane];
        unsigned long long x1lo = pk2(xv.x, xv.y);
        unsigned long long x1hi = pk2(xv.z, xv.w);

#pragma unroll
        for (int rr = 0; rr < 3; ++rr) {
            // tile row for di = 3g+rr-4 is (row+4+di) = row + 3g + rr
            const float4* rp = reinterpret_cast<const float4*>(&x2s[buf][row + 3 * g + rr][0]);
            float4 a0 = rp[lane];
            float4 a1 = rp[lane + 1];
            float4 a2 = rp[lane + 2];
            float v[12] = {a0.x, a0.y, a0.z, a0.w,
                           a1.x, a1.y, a1.z, a1.w,
                           a2.x, a2.y, a2.z, a2.w};
            unsigned long long pr[11];
#pragma unroll
            for (int t = 0; t < 11; ++t) pr[t] = pk2(v[t], v[t + 1]);
#pragma unroll
            for (int dj = 0; dj < 9; ++dj) {
                fma2(acc[(rr * 9 + dj) * 2 + 0], x1lo, pr[dj]);
                fma2(acc[(rr * 9 + dj) * 2 + 1], x1hi, pr[dj + 2]);
            }
        }
        __syncthreads();
    }

    // ---- epilogue: scale + scatter to k-maps ----
    const float inv = 1.0f / 81.0f;
    const int h = h0 + row;
#pragma unroll
    for (int rr = 0; rr < 3; ++rr) {
        const int di = 3 * g + rr - 4;
#pragma unroll
        for (int dj = 0; dj < 9; ++dj) {
            const int djv = dj - 4;
            const int t = 9 * di + djv;        // in [-40, 40]
            const int k = (81 - t) % 81;       // (-t) mod 81
            float l0, l1, u0, u1;
            upk2(acc[(rr * 9 + dj) * 2 + 0], l0, l1);
            upk2(acc[(rr * 9 + dj) * 2 + 1], u0, u1);
            float4 o = make_float4(l0 * inv, l1 * inv, u0 * inv, u1 * inv);
            float* dst = out + (((size_t)(bb * Dn + k) * Hn + h) * Wn + w0 + lane * 4);
            *reinterpret_cast<float4*>(dst) = o;
        }
    }
}

extern "C" void kernel_launch(void* const* d_in, const int* in_sizes, int n_in,
                              void* d_out, int out_size) {
    const float* x1 = (const float*)d_in[0];
    const float* x2 = (const float*)d_in[1];
    float* out = (float*)d_out;
    dim3 grid(Wn / TWt, Hn / TH, Bn);   // (2, 32, 4) = 256 blocks
    cost_volume_kernel<<<grid, NTHREADS>>>(x1, x2, out);
}

// round 3
// speedup vs baseline: 1.2441x; 1.2441x over previous
#include <cuda_runtime.h>
#include <cstdint>
#include <cstddef>

// Problem constants
#define Bn 4
#define Cn 128
#define Hn 128
#define Wn 256
#define Dn 81
#define HWn (Hn * Wn)
#define TH 4        // output rows per block
#define TWt 128     // output cols per block
#define NTHREADS 384
#define CPS 2       // channels per pipeline stage
#define NSTG (Cn / CPS)   // 64 stages, double-buffered

// f32x2 fma using native double register pairs (even-aligned, no packing cost)
__device__ __forceinline__ void fma2(double &d, double a, double b) {
    asm("fma.rn.f32x2 %0, %1, %2, %0;" : "+d"(d) : "d"(a), "d"(b));
}
// pack (lo = hi-half of a, hi = lo-half of b) -> odd-offset pair
__device__ __forceinline__ double mkodd(double a, double b) {
    return __hiloint2double(__double2loint(b), __double2hiint(a));
}
// cp.async 16B; src_sz=0 -> writes 16 zero bytes (used for halo)
__device__ __forceinline__ void cp16(void* dst_smem, const void* src, bool ok) {
    unsigned dst = (unsigned)__cvta_generic_to_shared(dst_smem);
    int sz = ok ? 16 : 0;
    asm volatile("cp.async.ca.shared.global [%0], [%1], 16, %2;" :: "r"(dst), "l"(src), "r"(sz));
}

__global__ void __launch_bounds__(NTHREADS, 1)
cost_volume_kernel(const float* __restrict__ x1,
                   const float* __restrict__ x2,
                   float* __restrict__ out)
{
    // double-buffered 2-channel stages: x2 tile rows h0-4..h0+7 (12) x 136 cols
    __shared__ __align__(16) float x2s[2][CPS][12][136];   // 2*2*6528B = 26112B
    __shared__ __align__(16) float x1s[2][CPS][TH][TWt];   // 2*2*2048B =  8192B

    const int tid  = threadIdx.x;
    const int lane = tid & 31;
    const int warp = tid >> 5;
    const int g    = warp >> 2;    // di-group 0..2
    const int row  = warp & 3;     // output row in tile

    const int w0 = blockIdx.x * TWt;
    const int h0 = blockIdx.y * TH;
    const int bb = blockIdx.z;

    double acc[54];
#pragma unroll
    for (int i = 0; i < 54; ++i) acc[i] = 0.0;

    // ---------- hoisted loader state (per thread, channel-invariant) ----------
    // chunk s=0: id = tid (always an x2 chunk, ids 0..383 of 408)
    // chunk s=1: id = tid+384 (x2 ids 384..407, x1 ids 408..535, else inactive)
    unsigned so0, so1 = 0;        // byte offset within (x2 or x1) channel slab
    long     go0, go1 = 0;        // byte offset within channel image (clamped if !ok)
    bool ok0, ok1 = false, act1 = false, isx1_1 = false;
    {
        int id = tid;
        int rw = id / 34, c4 = id - rw * 34;
        int hs = h0 - 4 + rw, ws = w0 - 4 + c4 * 4;
        ok0 = ((unsigned)hs < (unsigned)Hn) && ((unsigned)ws < (unsigned)Wn);
        go0 = ok0 ? (long)(hs * Wn + ws) * 4 : 0;
        so0 = (unsigned)(rw * 136 + c4 * 4) * 4;

        id = tid + NTHREADS;
        if (id < 408) {
            rw = id / 34; c4 = id - rw * 34;
            hs = h0 - 4 + rw; ws = w0 - 4 + c4 * 4;
            ok1 = ((unsigned)hs < (unsigned)Hn) && ((unsigned)ws < (unsigned)Wn);
            go1 = ok1 ? (long)(hs * Wn + ws) * 4 : 0;
            so1 = (unsigned)(rw * 136 + c4 * 4) * 4;
            act1 = true;
        } else if (id < 536) {
            int j = id - 408;
            rw = j >> 5; c4 = j & 31;
            ok1 = true;
            go1 = (long)((h0 + rw) * Wn + w0 + c4 * 4) * 4;
            so1 = (unsigned)(rw * TWt + c4 * 4) * 4;
            act1 = true; isx1_1 = true;
        }
    }
    // running global pointers (advance by one channel per channel)
    const char* gp0 = (const char*)(x2 + (size_t)bb * Cn * HWn) + go0;
    const char* gp1 = (const char*)((isx1_1 ? x1 : x2) + (size_t)bb * Cn * HWn) + go1;

    // per-channel x2 row byte offset for this warp (3 rows used, stride 544B)
    const unsigned rbase = (unsigned)(row + 3 * g) * 136u * 4u + (unsigned)lane * 16u;

    // loads one channel (global channel index implicit via running pointers)
    auto load_ch = [&](int buf, int slot) {
        char* b2 = (char*)&x2s[buf][slot][0][0];
        cp16(b2 + so0, gp0, ok0);
        gp0 += (size_t)HWn * 4;
        if (act1) {
            char* d1 = (isx1_1 ? (char*)&x1s[buf][slot][0][0] : b2) + so1;
            cp16(d1, gp1, ok1);
        }
        gp1 += (size_t)HWn * 4;
    };

    // prologue: stage 0 (channels 0,1)
    load_ch(0, 0);
    load_ch(0, 1);
    asm volatile("cp.async.commit_group;");

#pragma unroll 1
    for (int t = 0; t < NSTG; ++t) {
        const int buf = t & 1;
        if (t + 1 < NSTG) {
            load_ch(buf ^ 1, 0);
            load_ch(buf ^ 1, 1);
            asm volatile("cp.async.commit_group;");
            asm volatile("cp.async.wait_group 1;");
        } else {
            asm volatile("cp.async.wait_group 0;");
        }
        __syncthreads();

#pragma unroll
        for (int slot = 0; slot < CPS; ++slot) {
            const char* x2c = (const char*)&x2s[buf][slot][0][0] + rbase;
            const double2* x1r = reinterpret_cast<const double2*>(&x1s[buf][slot][row][0]);
            double2 xa = x1r[lane];   // (x0,x1),(x2,x3) as native f32x2 pairs

#pragma unroll
            for (int rr = 0; rr < 3; ++rr) {
                const char* rb = x2c + rr * (136 * 4);
                double2 q0 = *reinterpret_cast<const double2*>(rb);
                double2 q1 = *reinterpret_cast<const double2*>(rb + 16);
                double2 q2 = *reinterpret_cast<const double2*>(rb + 32);
                double prd[11];
                prd[0] = q0.x; prd[2] = q0.y; prd[4] = q1.x;
                prd[6] = q1.y; prd[8] = q2.x; prd[10] = q2.y;
                prd[1] = mkodd(q0.x, q0.y);
                prd[3] = mkodd(q0.y, q1.x);
                prd[5] = mkodd(q1.x, q1.y);
                prd[7] = mkodd(q1.y, q2.x);
                prd[9] = mkodd(q2.x, q2.y);
#pragma unroll
                for (int dj = 0; dj < 9; ++dj) {
                    fma2(acc[(rr * 9 + dj) * 2 + 0], xa.x, prd[dj]);
                    fma2(acc[(rr * 9 + dj) * 2 + 1], xa.y, prd[dj + 2]);
                }
            }
        }
        __syncthreads();   // before next iteration's loads overwrite buf^1... (writes target buf^1 which becomes buf next iter)
    }

    // ---------- epilogue: scale + scatter ----------
    const float inv = 1.0f / 81.0f;
    const int h = h0 + row;
#pragma unroll
    for (int rr = 0; rr < 3; ++rr) {
        const int di = 3 * g + rr - 4;
#pragma unroll
        for (int dj = 0; dj < 9; ++dj) {
            const int djv = dj - 4;
            const int tt = 9 * di + djv;
            const int k = (81 - tt) % 81;   // (-t) mod 81
            double alo = acc[(rr * 9 + dj) * 2 + 0];
            double ahi = acc[(rr * 9 + dj) * 2 + 1];
            float4 o;
            o.x = __int_as_float(__double2loint(alo)) * inv;
            o.y = __int_as_float(__double2hiint(alo)) * inv;
            o.z = __int_as_float(__double2loint(ahi)) * inv;
            o.w = __int_as_float(__double2hiint(ahi)) * inv;
            float* dst = out + (((size_t)(bb * Dn + k) * Hn + h) * Wn + w0 + lane * 4);
            *reinterpret_cast<float4*>(dst) = o;
        }
    }
}

extern "C" void kernel_launch(void* const* d_in, const int* in_sizes, int n_in,
                              void* d_out, int out_size) {
    const float* x1 = (const float*)d_in[0];
    const float* x2 = (const float*)d_in[1];
    float* out = (float*)d_out;
    dim3 grid(Wn / TWt, Hn / TH, Bn);   // (2, 32, 4) = 256 blocks
    cost_volume_kernel<<<grid, NTHREADS>>>(x1, x2, out);
}

// round 4
// speedup vs baseline: 1.2776x; 1.0270x over previous
#include <cuda_runtime.h>
#include <cstdint>
#include <cstddef>

// Problem constants
#define Bn 4
#define Cn 128
#define Hn 128
#define Wn 256
#define Dn 81
#define HWn (Hn * Wn)
#define TH 4        // output rows per block
#define TWt 128     // output cols per block
#define NTHREADS 384
#define CPS 2       // channels per pipeline stage
#define NSTG (Cn / CPS)

// pack two ADJACENT float regs into an f32x2 operand (folds to register pair)
__device__ __forceinline__ double pkd(float a, float b) {
    double d;
    asm("mov.b64 %0, {%1, %2};" : "=d"(d) : "f"(a), "f"(b));
    return d;
}
__device__ __forceinline__ void fma2(double &d, double a, double b) {
    asm("fma.rn.f32x2 %0, %1, %2, %0;" : "+d"(d) : "d"(a), "d"(b));
}
// cp.async 16B; src_sz=0 -> writes 16 zero bytes (halo fill)
__device__ __forceinline__ void cp16(void* dst_smem, const void* src, bool ok) {
    unsigned dst = (unsigned)__cvta_generic_to_shared(dst_smem);
    int sz = ok ? 16 : 0;
    asm volatile("cp.async.ca.shared.global [%0], [%1], 16, %2;" :: "r"(dst), "l"(src), "r"(sz));
}

__global__ void __launch_bounds__(NTHREADS, 1)
cost_volume_kernel(const float* __restrict__ x1,
                   const float* __restrict__ x2,
                   float* __restrict__ out)
{
    __shared__ __align__(16) float x2s[2][CPS][12][136];
    __shared__ __align__(16) float x1s[2][CPS][TH][TWt];

    const int tid  = threadIdx.x;
    const int lane = tid & 31;
    const int warp = tid >> 5;
    const int g    = warp >> 2;    // di-group 0..2
    const int row  = warp & 3;     // output row in tile

    const int w0 = blockIdx.x * TWt;
    const int h0 = blockIdx.y * TH;
    const int bb = blockIdx.z;

    // even-dj accumulators: [rr][ej][lo/hi] as f32x2
    double acc_e[30];
    // odd-dj accumulators:  [rr][oj][px] scalars
    float  acc_o[48];
#pragma unroll
    for (int i = 0; i < 30; ++i) acc_e[i] = 0.0;
#pragma unroll
    for (int i = 0; i < 48; ++i) acc_o[i] = 0.0f;

    // ---------- hoisted loader state (channel-invariant) ----------
    unsigned so0, so1 = 0;
    long     go0, go1 = 0;
    bool ok0, ok1 = false, act1 = false, isx1_1 = false;
    {
        int id = tid;
        int rw = id / 34, c4 = id - rw * 34;
        int hs = h0 - 4 + rw, ws = w0 - 4 + c4 * 4;
        ok0 = ((unsigned)hs < (unsigned)Hn) && ((unsigned)ws < (unsigned)Wn);
        go0 = ok0 ? (long)(hs * Wn + ws) * 4 : 0;
        so0 = (unsigned)(rw * 136 + c4 * 4) * 4;

        id = tid + NTHREADS;
        if (id < 408) {
            rw = id / 34; c4 = id - rw * 34;
            hs = h0 - 4 + rw; ws = w0 - 4 + c4 * 4;
            ok1 = ((unsigned)hs < (unsigned)Hn) && ((unsigned)ws < (unsigned)Wn);
            go1 = ok1 ? (long)(hs * Wn + ws) * 4 : 0;
            so1 = (unsigned)(rw * 136 + c4 * 4) * 4;
            act1 = true;
        } else if (id < 536) {
            int j = id - 408;
            rw = j >> 5; c4 = j & 31;
            ok1 = true;
            go1 = (long)((h0 + rw) * Wn + w0 + c4 * 4) * 4;
            so1 = (unsigned)(rw * TWt + c4 * 4) * 4;
            act1 = true; isx1_1 = true;
        }
    }
    const char* gp0 = (const char*)(x2 + (size_t)bb * Cn * HWn) + go0;
    const char* gp1 = (const char*)((isx1_1 ? x1 : x2) + (size_t)bb * Cn * HWn) + go1;

    const unsigned rbase = (unsigned)(row + 3 * g) * 136u * 4u + (unsigned)lane * 16u;

    auto load_ch = [&](int buf, int slot) {
        char* b2 = (char*)&x2s[buf][slot][0][0];
        cp16(b2 + so0, gp0, ok0);
        gp0 += (size_t)HWn * 4;
        if (act1) {
            char* d1 = (isx1_1 ? (char*)&x1s[buf][slot][0][0] : b2) + so1;
            cp16(d1, gp1, ok1);
        }
        gp1 += (size_t)HWn * 4;
    };

    load_ch(0, 0);
    load_ch(0, 1);
    asm volatile("cp.async.commit_group;");

#pragma unroll 1
    for (int t = 0; t < NSTG; ++t) {
        const int buf = t & 1;
        if (t + 1 < NSTG) {
            load_ch(buf ^ 1, 0);
            load_ch(buf ^ 1, 1);
            asm volatile("cp.async.commit_group;");
            asm volatile("cp.async.wait_group 1;");
        } else {
            asm volatile("cp.async.wait_group 0;");
        }
        __syncthreads();

#pragma unroll
        for (int slot = 0; slot < CPS; ++slot) {
            const float4* xr = reinterpret_cast<const float4*>(&x1s[buf][slot][row][0]);
            float4 xv = xr[lane];
            float xs[4] = {xv.x, xv.y, xv.z, xv.w};
            double xlo = pkd(xv.x, xv.y);
            double xhi = pkd(xv.z, xv.w);

            const char* base = (const char*)&x2s[buf][slot][0][0] + rbase;
#pragma unroll
            for (int rr = 0; rr < 3; ++rr) {
                const float4* rp = reinterpret_cast<const float4*>(base + rr * (136 * 4));
                float4 q0 = rp[0], q1 = rp[1], q2 = rp[2];
                float v[12] = {q0.x, q0.y, q0.z, q0.w,
                               q1.x, q1.y, q1.z, q1.w,
                               q2.x, q2.y, q2.z, q2.w};
                // even dj: natural aligned pairs (v[dj],v[dj+1]) with dj even
#pragma unroll
                for (int e = 0; e < 5; ++e) {
                    const int dj = 2 * e;
                    fma2(acc_e[(rr * 5 + e) * 2 + 0], xlo, pkd(v[dj],     v[dj + 1]));
                    fma2(acc_e[(rr * 5 + e) * 2 + 1], xhi, pkd(v[dj + 2], v[dj + 3]));
                }
                // odd dj: pure scalar FFMAs, no packing
#pragma unroll
                for (int o = 0; o < 4; ++o) {
                    const int dj = 2 * o + 1;
#pragma unroll
                    for (int p = 0; p < 4; ++p)
                        acc_o[(rr * 4 + o) * 4 + p] =
                            fmaf(xs[p], v[dj + p], acc_o[(rr * 4 + o) * 4 + p]);
                }
            }
        }
        __syncthreads();
    }

    // ---------- epilogue: scale + scatter ----------
    const float inv = 1.0f / 81.0f;
    const int h = h0 + row;
    const int di = 3 * g - 4;   // + rr below
#pragma unroll
    for (int rr = 0; rr < 3; ++rr) {
#pragma unroll
        for (int e = 0; e < 5; ++e) {
            const int djv = 2 * e - 4;
            const int tt = 9 * (di + rr) + djv;
            const int k = (81 - tt) % 81;
            double alo = acc_e[(rr * 5 + e) * 2 + 0];
            double ahi = acc_e[(rr * 5 + e) * 2 + 1];
            float4 o;
            o.x = __int_as_float(__double2loint(alo)) * inv;
            o.y = __int_as_float(__double2hiint(alo)) * inv;
            o.z = __int_as_float(__double2loint(ahi)) * inv;
            o.w = __int_as_float(__double2hiint(ahi)) * inv;
            float* dst = out + (((size_t)(bb * Dn + k) * Hn + h) * Wn + w0 + lane * 4);
            *reinterpret_cast<float4*>(dst) = o;
        }
#pragma unroll
        for (int ojj = 0; ojj < 4; ++ojj) {
            const int djv = 2 * ojj - 3;
            const int tt = 9 * (di + rr) + djv;
            const int k = (81 - tt) % 81;
            float4 o;
            o.x = acc_o[(rr * 4 + ojj) * 4 + 0] * inv;
            o.y = acc_o[(rr * 4 + ojj) * 4 + 1] * inv;
            o.z = acc_o[(rr * 4 + ojj) * 4 + 2] * inv;
            o.w = acc_o[(rr * 4 + ojj) * 4 + 3] * inv;
            float* dst = out + (((size_t)(bb * Dn + k) * Hn + h) * Wn + w0 + lane * 4);
            *reinterpret_cast<float4*>(dst) = o;
        }
    }
}

extern "C" void kernel_launch(void* const* d_in, const int* in_sizes, int n_in,
                              void* d_out, int out_size) {
    const float* x1 = (const float*)d_in[0];
    const float* x2 = (const float*)d_in[1];
    float* out = (float*)d_out;
    dim3 grid(Wn / TWt, Hn / TH, Bn);   // (2, 32, 4) = 256 blocks
    cost_volume_kernel<<<grid, NTHREADS>>>(x1, x2, out);
}